// round 3
// baseline (speedup 1.0000x reference)
#include <cuda_runtime.h>
#include <cstdint>

// Problem constants
constexpr int T_ = 1024;
constexpr int B_ = 32;
constexpr int D_ = 1024;
constexpr int M_ = T_ * B_;        // 32768 rows for the precompute GEMMs

// Scratch for precomputed xRx (which=0) and xWd (which=1)
__device__ float g_scratch[2][(size_t)M_ * D_];

// ---------------------------------------------------------------------------
// Precompute GEMM: C[m][n] = sum_k A[m][k] * W[n][k] + bias[n]
// A: [M_, D_] row-major (x flattened), W: [D_, D_] row-major.
// 64x64 block tile, 16 k-tile, 256 threads, 4x4 per-thread micro-tile.
// ---------------------------------------------------------------------------
__global__ void __launch_bounds__(256) gemm_bias_kernel(
    const float* __restrict__ A, const float* __restrict__ W,
    const float* __restrict__ bias, int which)
{
    float* C = g_scratch[which];
    __shared__ float As[16][64];
    __shared__ float Ws[16][64];

    const int m0 = blockIdx.y * 64;
    const int n0 = blockIdx.x * 64;
    const int tid = threadIdx.x;

    const int lm = tid >> 2;          // 0..63  (row within tile for loading)
    const int lk = (tid & 3) << 2;    // 0,4,8,12 (k offset, float4)
    const int tr = (tid >> 4) << 2;   // 0..60 step 4 (compute row base)
    const int tc = (tid & 15) << 2;   // 0..60 step 4 (compute col base)

    float acc[4][4];
#pragma unroll
    for (int i = 0; i < 4; i++)
#pragma unroll
        for (int j = 0; j < 4; j++) acc[i][j] = 0.f;

    for (int k0 = 0; k0 < D_; k0 += 16) {
        float4 a = *(const float4*)&A[(size_t)(m0 + lm) * D_ + k0 + lk];
        float4 w = *(const float4*)&W[(size_t)(n0 + lm) * D_ + k0 + lk];
        As[lk + 0][lm] = a.x; As[lk + 1][lm] = a.y;
        As[lk + 2][lm] = a.z; As[lk + 3][lm] = a.w;
        Ws[lk + 0][lm] = w.x; Ws[lk + 1][lm] = w.y;
        Ws[lk + 2][lm] = w.z; Ws[lk + 3][lm] = w.w;
        __syncthreads();
#pragma unroll
        for (int k = 0; k < 16; k++) {
            float4 av = *(const float4*)&As[k][tr];
            float4 wv = *(const float4*)&Ws[k][tc];
            float ar[4] = {av.x, av.y, av.z, av.w};
            float wr[4] = {wv.x, wv.y, wv.z, wv.w};
#pragma unroll
            for (int i = 0; i < 4; i++)
#pragma unroll
                for (int j = 0; j < 4; j++)
                    acc[i][j] = fmaf(ar[i], wr[j], acc[i][j]);
        }
        __syncthreads();
    }

    float4 bv = *(const float4*)&bias[n0 + tc];
#pragma unroll
    for (int i = 0; i < 4; i++) {
        float4 o = make_float4(acc[i][0] + bv.x, acc[i][1] + bv.y,
                               acc[i][2] + bv.z, acc[i][3] + bv.w);
        *(float4*)&C[(size_t)(m0 + tr + i) * D_ + n0 + tc] = o;
    }
}

// ---------------------------------------------------------------------------
// h0 -> H[0]
// ---------------------------------------------------------------------------
__global__ void copy_h0_kernel(const float* __restrict__ h0, float* __restrict__ H)
{
    int i = blockIdx.x * blockDim.x + threadIdx.x;
    if (i < B_ * D_) H[i] = h0[i];
}

// ---------------------------------------------------------------------------
// Persistent recurrent scan.
// 128 CTAs (one per SM, all co-resident), 256 threads each.
// CTA owns 8 output columns (for both R_h and R_delta), weights cached in SMEM
// once. Per step: stage h_prev (transposed, padded) in SMEM, each warp computes
// one column's two 1024-length dots for all 32 batches, applies gates, writes
// h_new + out, then a grid-wide sense barrier.
// ---------------------------------------------------------------------------
constexpr int NCTA = 128;
constexpr int JC = D_ / NCTA;               // 8 columns per CTA
constexpr int HS_STRIDE = 33;               // pad to kill bank conflicts
constexpr int SMEM_FLOATS = 2 * JC * D_ + D_ * HS_STRIDE;
constexpr int SMEM_BYTES = SMEM_FLOATS * 4; // 200704 B < 227 KB

__device__ unsigned g_bar_count = 0;
__device__ unsigned g_bar_gen = 0;

__global__ void __launch_bounds__(256, 1) scan_kernel(
    const float* __restrict__ x,
    const float* __restrict__ Rh,
    const float* __restrict__ Rd,
    const float* __restrict__ bgate,
    float* __restrict__ out,
    float* __restrict__ H)
{
    extern __shared__ float sm[];
    float* wv = sm;                    // [JC][D_]  R_h rows for owned columns
    float* wd = sm + JC * D_;          // [JC][D_]  R_delta rows
    float* hs = sm + 2 * JC * D_;      // [D_][HS_STRIDE] transposed h_prev

    const float* __restrict__ xr = g_scratch[0];
    const float* __restrict__ xw = g_scratch[1];

    const int cta = blockIdx.x;
    const int tid = threadIdx.x;
    const int j0 = cta * JC;

    // Cache this CTA's weight rows once (contiguous rows of Rh / Rd).
    for (int i = tid; i < JC * D_ / 4; i += 256) {
        ((float4*)wv)[i] = ((const float4*)(Rh + (size_t)j0 * D_))[i];
        ((float4*)wd)[i] = ((const float4*)(Rd + (size_t)j0 * D_))[i];
    }

    unsigned gen = *((volatile unsigned*)&g_bar_gen);

    const int wj = tid >> 5;      // warp id -> local column
    const int b  = tid & 31;      // lane -> batch
    const int j  = j0 + wj;       // global column
    const float bg = bgate[j];

    for (int t = 0; t < T_; t++) {
        // Stage h_prev = H[t] into SMEM, transposed: hs[d][b].
        // __ldcg: bypass L1 so cross-SM writes from the previous step are seen.
        const float4* hp = (const float4*)(H + (size_t)t * B_ * D_);
        for (int i = tid; i < B_ * D_ / 4; i += 256) {
            float4 v = __ldcg(hp + i);
            int bb = i >> 8;              // batch row
            int dd = (i & 255) << 2;      // d base
            hs[(dd + 0) * HS_STRIDE + bb] = v.x;
            hs[(dd + 1) * HS_STRIDE + bb] = v.y;
            hs[(dd + 2) * HS_STRIDE + bb] = v.z;
            hs[(dd + 3) * HS_STRIDE + bb] = v.w;
        }
        __syncthreads();

        const size_t base = (size_t)t * B_ * D_ + (size_t)b * D_ + j;
        float accv = xr[base];
        float accd = xw[base];

        const float4* wv4 = (const float4*)(wv + wj * D_);
        const float4* wd4 = (const float4*)(wd + wj * D_);
#pragma unroll 8
        for (int d4 = 0; d4 < D_ / 4; d4++) {
            float4 a = wv4[d4];
            float4 c = wd4[d4];
            int di = d4 << 2;
            float h0v = hs[(di + 0) * HS_STRIDE + b];
            float h1v = hs[(di + 1) * HS_STRIDE + b];
            float h2v = hs[(di + 2) * HS_STRIDE + b];
            float h3v = hs[(di + 3) * HS_STRIDE + b];
            accv = fmaf(h0v, a.x, accv);  accd = fmaf(h0v, c.x, accd);
            accv = fmaf(h1v, a.y, accv);  accd = fmaf(h1v, c.y, accd);
            accv = fmaf(h2v, a.z, accv);  accd = fmaf(h2v, c.z, accd);
            accv = fmaf(h3v, a.w, accv);  accd = fmaf(h3v, c.w, accd);
        }

        float hprev = hs[j * HS_STRIDE + b];
        float delta = 1.f / (1.f + __expf(-accd));
        float hv    = tanhf(accv);
        float hn    = hprev + delta * (hv - hprev);   // (1-d)*hp + d*tanh(v)
        float g     = hn + x[base] + bg;
        float sil   = g / (1.f + __expf(-g));         // silu(g)
        out[base] = hn * sil;
        H[base + (size_t)B_ * D_] = hn;               // H[t+1]

        // ---- grid-wide barrier ----
        __threadfence();
        __syncthreads();
        if (tid == 0) {
            unsigned arr = atomicAdd(&g_bar_count, 1u);
            if (arr == NCTA - 1) {
                g_bar_count = 0u;
                __threadfence();
                atomicAdd(&g_bar_gen, 1u);
            } else {
                while (*((volatile unsigned*)&g_bar_gen) == gen) { }
            }
        }
        gen++;
        __syncthreads();
        __threadfence();
    }
}

// ---------------------------------------------------------------------------
// Launch
// Inputs (metadata order): x, h0, R_h, R_x, R_delta, W_delta, b, b_delta, b_gate
// Output: outputs [T,B,D] followed by h [T+1,B,D], fp32.
// ---------------------------------------------------------------------------
extern "C" void kernel_launch(void* const* d_in, const int* in_sizes, int n_in,
                              void* d_out, int out_size)
{
    const float* x       = (const float*)d_in[0];
    const float* h0      = (const float*)d_in[1];
    const float* R_h     = (const float*)d_in[2];
    const float* R_x     = (const float*)d_in[3];
    const float* R_delta = (const float*)d_in[4];
    const float* W_delta = (const float*)d_in[5];
    const float* b       = (const float*)d_in[6];
    const float* b_delta = (const float*)d_in[7];
    const float* b_gate  = (const float*)d_in[8];

    float* out = (float*)d_out;
    float* H   = out + (size_t)T_ * B_ * D_;   // h region: [T+1, B, D]

    cudaFuncSetAttribute(scan_kernel,
                         cudaFuncAttributeMaxDynamicSharedMemorySize, SMEM_BYTES);

    dim3 ggrid(D_ / 64, M_ / 64);
    gemm_bias_kernel<<<ggrid, 256>>>(x, R_x,     b,       0);  // xRx
    gemm_bias_kernel<<<ggrid, 256>>>(x, W_delta, b_delta, 1);  // xWd
    copy_h0_kernel<<<(B_ * D_ + 255) / 256, 256>>>(h0, H);
    scan_kernel<<<NCTA, 256, SMEM_BYTES>>>(x, R_h, R_delta, b_gate, out, H);
}

// round 4
// speedup vs baseline: 1.6308x; 1.6308x over previous
#include <cuda_runtime.h>
#include <cstdint>

// Problem constants
constexpr int T_ = 1024;
constexpr int B_ = 32;
constexpr int D_ = 1024;
constexpr int M_ = T_ * B_;        // 32768 rows for the precompute GEMMs

// Scratch for precomputed xRx ([0]) and xWd ([1])
__device__ float g_scratch[2][(size_t)M_ * D_];

// ---------------------------------------------------------------------------
// Precompute GEMM: C[m][n] = sum_k A[m][k] * W[n][k] + bias[n]
// 128x128 block tile, k-tile 8, 256 threads, 8x8 per-thread microtile,
// double-buffered SMEM. blockIdx.z selects (W,bias,C) pair so both GEMMs
// run in one launch and share A through L2.
// ---------------------------------------------------------------------------
constexpr int BM = 128, BN = 128, BK = 8;

__global__ void __launch_bounds__(256) gemm_bias_kernel(
    const float* __restrict__ A,
    const float* __restrict__ W0, const float* __restrict__ W1,
    const float* __restrict__ b0, const float* __restrict__ b1)
{
    const float* __restrict__ W    = blockIdx.z ? W1 : W0;
    const float* __restrict__ bias = blockIdx.z ? b1 : b0;
    float* __restrict__ C = g_scratch[blockIdx.z];

    __shared__ float As[2][BK][BM];
    __shared__ float Ws[2][BK][BN];

    const int m0 = blockIdx.y * BM;
    const int n0 = blockIdx.x * BN;
    const int tid = threadIdx.x;

    // loader mapping: each thread loads one float4 of A and one of W per k-tile
    const int lrow = tid >> 1;            // 0..127
    const int lk   = (tid & 1) << 2;      // 0 or 4

    // compute mapping: 8 warps as 4(m) x 2(n); lane as 4(trow) x 8(tcol)
    const int wid  = tid >> 5;
    const int lane = tid & 31;
    const int wm   = (wid & 3) * 32;
    const int wn   = (wid >> 2) * 64;
    const int trow = (lane >> 3) << 2;    // 0,4,8,12
    const int tcol = (lane & 7) << 2;     // 0..28

    float acc[8][8];
#pragma unroll
    for (int i = 0; i < 8; i++)
#pragma unroll
        for (int jj = 0; jj < 8; jj++) acc[i][jj] = 0.f;

    const float* Aptr = A + (size_t)(m0 + lrow) * D_ + lk;
    const float* Wptr = W + (size_t)(n0 + lrow) * D_ + lk;

    // prologue: tile 0 -> buffer 0
    {
        float4 ra = *(const float4*)Aptr;
        float4 rw = *(const float4*)Wptr;
        As[0][lk + 0][lrow] = ra.x; As[0][lk + 1][lrow] = ra.y;
        As[0][lk + 2][lrow] = ra.z; As[0][lk + 3][lrow] = ra.w;
        Ws[0][lk + 0][lrow] = rw.x; Ws[0][lk + 1][lrow] = rw.y;
        Ws[0][lk + 2][lrow] = rw.z; Ws[0][lk + 3][lrow] = rw.w;
    }
    __syncthreads();

    constexpr int NKT = D_ / BK;
    int buf = 0;
    for (int kt = 1; kt <= NKT; kt++) {
        float4 na, nw;
        if (kt < NKT) {
            na = *(const float4*)(Aptr + kt * BK);
            nw = *(const float4*)(Wptr + kt * BK);
        }
#pragma unroll
        for (int k = 0; k < BK; k++) {
            float4 a0 = *(const float4*)&As[buf][k][wm + trow];
            float4 a1 = *(const float4*)&As[buf][k][wm + 16 + trow];
            float4 w0 = *(const float4*)&Ws[buf][k][wn + tcol];
            float4 w1 = *(const float4*)&Ws[buf][k][wn + 32 + tcol];
            float av[8] = {a0.x, a0.y, a0.z, a0.w, a1.x, a1.y, a1.z, a1.w};
            float wv[8] = {w0.x, w0.y, w0.z, w0.w, w1.x, w1.y, w1.z, w1.w};
#pragma unroll
            for (int i = 0; i < 8; i++)
#pragma unroll
                for (int jj = 0; jj < 8; jj++)
                    acc[i][jj] = fmaf(av[i], wv[jj], acc[i][jj]);
        }
        if (kt < NKT) {
            int nb = buf ^ 1;
            As[nb][lk + 0][lrow] = na.x; As[nb][lk + 1][lrow] = na.y;
            As[nb][lk + 2][lrow] = na.z; As[nb][lk + 3][lrow] = na.w;
            Ws[nb][lk + 0][lrow] = nw.x; Ws[nb][lk + 1][lrow] = nw.y;
            Ws[nb][lk + 2][lrow] = nw.z; Ws[nb][lk + 3][lrow] = nw.w;
        }
        __syncthreads();
        buf ^= 1;
    }

    float4 bb0 = *(const float4*)&bias[n0 + wn + tcol];
    float4 bb1 = *(const float4*)&bias[n0 + wn + 32 + tcol];
#pragma unroll
    for (int i = 0; i < 8; i++) {
        int mi = wm + ((i < 4) ? (trow + i) : (16 + trow + i - 4));
        float* cp = C + (size_t)(m0 + mi) * D_ + n0;
        float4 o0 = make_float4(acc[i][0] + bb0.x, acc[i][1] + bb0.y,
                                acc[i][2] + bb0.z, acc[i][3] + bb0.w);
        float4 o1 = make_float4(acc[i][4] + bb1.x, acc[i][5] + bb1.y,
                                acc[i][6] + bb1.z, acc[i][7] + bb1.w);
        *(float4*)(cp + wn + tcol) = o0;
        *(float4*)(cp + wn + 32 + tcol) = o1;
    }
}

// ---------------------------------------------------------------------------
// h0 -> H[0]
// ---------------------------------------------------------------------------
__global__ void copy_h0_kernel(const float* __restrict__ h0, float* __restrict__ H)
{
    int i = blockIdx.x * blockDim.x + threadIdx.x;
    if (i < B_ * D_) H[i] = h0[i];
}

// ---------------------------------------------------------------------------
// Persistent recurrent scan.
// 128 CTAs x 512 threads. CTA owns 8 columns of R_h and R_delta (SMEM-cached
// once). Per step: stage h_prev as float4 rows [b][d4] (stride 257 float4,
// conflict-free 4-phase LDS.128), 16 warps = 8 columns x 2 K-halves, smem
// reduction, gates, flag-array global barrier.
// ---------------------------------------------------------------------------
constexpr int NCTA = 128;
constexpr int JC = D_ / NCTA;               // 8 columns per CTA
constexpr int SB_ = 512;                    // threads per CTA
constexpr int WV_F = JC * D_;               // 8192 floats per weight matrix
constexpr int H4_STRIDE = 257;              // float4 stride per batch row
constexpr int HS_F = B_ * H4_STRIDE * 4;    // 32896 floats
constexpr int RED_F = 2 * JC * B_;          // 512 floats
constexpr int SMEM_FLOATS = 2 * WV_F + HS_F + RED_F;
constexpr int SMEM_BYTES = SMEM_FLOATS * 4; // 199168 B < 227 KB

__device__ volatile unsigned g_arrive[NCTA * 32];  // one flag per CTA, 128B apart
__device__ volatile unsigned g_release;

__global__ void __launch_bounds__(SB_, 1) scan_kernel(
    const float* __restrict__ x,
    const float* __restrict__ Rh,
    const float* __restrict__ Rd,
    const float* __restrict__ bgate,
    float* __restrict__ out,
    float* __restrict__ H)
{
    extern __shared__ float sm[];
    float* wv   = sm;                        // [JC][D_] R_h rows
    float* wd   = sm + WV_F;                 // [JC][D_] R_delta rows
    float* hsf  = sm + 2 * WV_F;             // h as [B][257*4] floats
    float4* hs4 = (float4*)hsf;
    float* red  = sm + 2 * WV_F + HS_F;      // [2][JC][B_] partial sums

    const float* __restrict__ xr = g_scratch[0];
    const float* __restrict__ xw = g_scratch[1];

    const int cta = blockIdx.x;
    const int tid = threadIdx.x;
    const int j0 = cta * JC;

    // Cache this CTA's weight rows once.
    for (int i = tid; i < WV_F / 4; i += SB_) {
        ((float4*)wv)[i] = ((const float4*)(Rh + (size_t)j0 * D_))[i];
        ((float4*)wd)[i] = ((const float4*)(Rd + (size_t)j0 * D_))[i];
    }

    const int warp = tid >> 5;
    const int b    = tid & 31;       // lane -> batch
    const int wj   = warp & 7;       // local column
    const int half = warp >> 3;      // K-half
    const int j    = j0 + wj;        // global column
    const float bg = bgate[j];

    const float4* wv4 = (const float4*)(wv + wj * D_) + half * 128;
    const float4* wd4 = (const float4*)(wd + wj * D_) + half * 128;
    const float4* h4p = hs4 + b * H4_STRIDE + half * 128;

    for (int t = 0; t < T_; t++) {
        // ---- stage h_prev = H[t] into SMEM as [b][d4] float4 rows ----
        const float4* hp = (const float4*)(H + (size_t)t * B_ * D_);
#pragma unroll
        for (int i = tid; i < B_ * D_ / 4; i += SB_) {
            float4 v = __ldcg(hp + i);
            int bb = i >> 8;            // batch row
            int f  = i & 255;           // float4 index within row
            hs4[bb * H4_STRIDE + f] = v;
        }
        __syncthreads();

        const size_t base = (size_t)t * B_ * D_ + (size_t)b * D_ + j;
        float av0, ad0;
        if (half == 0) { av0 = xr[base]; ad0 = xw[base]; }
        else           { av0 = 0.f;      ad0 = 0.f; }
        float av1 = 0.f, ad1 = 0.f;

#pragma unroll 8
        for (int q = 0; q < 128; q += 2) {
            float4 h0 = h4p[q];
            float4 h1 = h4p[q + 1];
            float4 a0 = wv4[q];
            float4 a1 = wv4[q + 1];
            float4 c0 = wd4[q];
            float4 c1 = wd4[q + 1];
            av0 = fmaf(h0.x, a0.x, av0);  ad0 = fmaf(h0.x, c0.x, ad0);
            av0 = fmaf(h0.y, a0.y, av0);  ad0 = fmaf(h0.y, c0.y, ad0);
            av0 = fmaf(h0.z, a0.z, av0);  ad0 = fmaf(h0.z, c0.z, ad0);
            av0 = fmaf(h0.w, a0.w, av0);  ad0 = fmaf(h0.w, c0.w, ad0);
            av1 = fmaf(h1.x, a1.x, av1);  ad1 = fmaf(h1.x, c1.x, ad1);
            av1 = fmaf(h1.y, a1.y, av1);  ad1 = fmaf(h1.y, c1.y, ad1);
            av1 = fmaf(h1.z, a1.z, av1);  ad1 = fmaf(h1.z, c1.z, ad1);
            av1 = fmaf(h1.w, a1.w, av1);  ad1 = fmaf(h1.w, c1.w, ad1);
        }
        float accv = av0 + av1;
        float accd = ad0 + ad1;

        if (half == 1) {
            red[wj * B_ + b]           = accv;
            red[JC * B_ + wj * B_ + b] = accd;
        }
        __syncthreads();

        if (half == 0) {
            accv += red[wj * B_ + b];
            accd += red[JC * B_ + wj * B_ + b];
            float hprev = hsf[b * (H4_STRIDE * 4) + j];
            float delta = 1.f / (1.f + __expf(-accd));
            float hv    = tanhf(accv);
            float hn    = hprev + delta * (hv - hprev);   // (1-d)*hp + d*tanh(v)
            float g     = hn + x[base] + bg;
            float sil   = g / (1.f + __expf(-g));         // silu(g)
            out[base] = hn * sil;
            H[base + (size_t)B_ * D_] = hn;               // H[t+1]
        }

        // ---- grid-wide barrier: flag array + master warp + release word ----
        __threadfence();
        __syncthreads();
        const unsigned want = (unsigned)(t + 1);
        if (tid == 0) g_arrive[cta << 5] = want;
        if (cta == 0 && tid >= 32 && tid < 64) {
            int l = tid - 32;                 // each lane watches 4 CTA flags
            bool ok;
            do {
                ok = (g_arrive[(l * 4 + 0) << 5] == want)
                  && (g_arrive[(l * 4 + 1) << 5] == want)
                  && (g_arrive[(l * 4 + 2) << 5] == want)
                  && (g_arrive[(l * 4 + 3) << 5] == want);
            } while (!__all_sync(0xffffffffu, ok));
            if (l == 0) { __threadfence(); g_release = want; }
        }
        if (tid == 0) {
            while (g_release != want) { __nanosleep(32); }
        }
        __syncthreads();
        __threadfence();
    }
}

// ---------------------------------------------------------------------------
// Launch
// Inputs (metadata order): x, h0, R_h, R_x, R_delta, W_delta, b, b_delta, b_gate
// Output: outputs [T,B,D] followed by h [T+1,B,D], fp32.
// ---------------------------------------------------------------------------
extern "C" void kernel_launch(void* const* d_in, const int* in_sizes, int n_in,
                              void* d_out, int out_size)
{
    const float* x       = (const float*)d_in[0];
    const float* h0      = (const float*)d_in[1];
    const float* R_h     = (const float*)d_in[2];
    const float* R_x     = (const float*)d_in[3];
    const float* R_delta = (const float*)d_in[4];
    const float* W_delta = (const float*)d_in[5];
    const float* b       = (const float*)d_in[6];
    const float* b_delta = (const float*)d_in[7];
    const float* b_gate  = (const float*)d_in[8];

    float* out = (float*)d_out;
    float* H   = out + (size_t)T_ * B_ * D_;   // h region: [T+1, B, D]

    cudaFuncSetAttribute(scan_kernel,
                         cudaFuncAttributeMaxDynamicSharedMemorySize, SMEM_BYTES);

    dim3 ggrid(D_ / BN, M_ / BM, 2);
    gemm_bias_kernel<<<ggrid, 256>>>(x, R_x, W_delta, b, b_delta);
    copy_h0_kernel<<<(B_ * D_ + 255) / 256, 256>>>(h0, H);
    scan_kernel<<<NCTA, SB_, SMEM_BYTES>>>(x, R_h, R_delta, b_gate, out, H);
}

// round 5
// speedup vs baseline: 2.2285x; 1.3665x over previous
#include <cuda_runtime.h>
#include <cstdint>

// Problem constants
constexpr int T_ = 1024;
constexpr int B_ = 32;
constexpr int D_ = 1024;
constexpr int M_ = T_ * B_;        // 32768 rows for the precompute GEMMs

// Scratch for precomputed xRx ([0]) and xWd ([1])
__device__ float g_scratch[2][(size_t)M_ * D_];

// ---------------------------------------------------------------------------
// Packed f32x2 helpers (sm_103a): one instruction = two fp32 FMAs.
// ---------------------------------------------------------------------------
__device__ __forceinline__ void fma2(unsigned long long& d,
                                     unsigned long long a,
                                     unsigned long long b) {
    asm("fma.rn.f32x2 %0, %1, %2, %0;" : "+l"(d) : "l"(a), "l"(b));
}
__device__ __forceinline__ unsigned long long dup2(float x) {
    unsigned long long r;
    asm("mov.b64 %0, {%1, %1};" : "=l"(r) : "f"(x));
    return r;
}
__device__ __forceinline__ float2 unpk(unsigned long long v) {
    float2 r;
    asm("mov.b64 {%0, %1}, %2;" : "=f"(r.x), "=f"(r.y) : "l"(v));
    return r;
}

// ---------------------------------------------------------------------------
// Precompute GEMM: C[m][n] = sum_k A[m][k] * W[n][k] + bias[n]
// 128x128 tile, k-tile 8, 256 threads, 8x8 microtile held as 8x4 f32x2
// packed accumulators, double-buffered SMEM. blockIdx.z selects the
// (W, bias, C) pair so both GEMMs share A through L2.
// ---------------------------------------------------------------------------
constexpr int BM = 128, BN = 128, BK = 8;

__global__ void __launch_bounds__(256) gemm_bias_kernel(
    const float* __restrict__ A,
    const float* __restrict__ W0, const float* __restrict__ W1,
    const float* __restrict__ b0, const float* __restrict__ b1)
{
    const float* __restrict__ W    = blockIdx.z ? W1 : W0;
    const float* __restrict__ bias = blockIdx.z ? b1 : b0;
    float* __restrict__ C = g_scratch[blockIdx.z];

    __shared__ float As[2][BK][BM];
    __shared__ float Ws[2][BK][BN];

    const int m0 = blockIdx.y * BM;
    const int n0 = blockIdx.x * BN;
    const int tid = threadIdx.x;

    const int lrow = tid >> 1;            // 0..127
    const int lk   = (tid & 1) << 2;      // 0 or 4

    const int wid  = tid >> 5;
    const int lane = tid & 31;
    const int wm   = (wid & 3) * 32;
    const int wn   = (wid >> 2) * 64;
    const int trow = (lane >> 3) << 2;    // 0,4,8,12
    const int tcol = (lane & 7) << 2;     // 0..28

    // acc2[i][p]: packed pair of adjacent n-columns
    unsigned long long acc2[8][4];
#pragma unroll
    for (int i = 0; i < 8; i++)
#pragma unroll
        for (int p = 0; p < 4; p++) acc2[i][p] = 0ull;

    const float* Aptr = A + (size_t)(m0 + lrow) * D_ + lk;
    const float* Wptr = W + (size_t)(n0 + lrow) * D_ + lk;

    {
        float4 ra = *(const float4*)Aptr;
        float4 rw = *(const float4*)Wptr;
        As[0][lk + 0][lrow] = ra.x; As[0][lk + 1][lrow] = ra.y;
        As[0][lk + 2][lrow] = ra.z; As[0][lk + 3][lrow] = ra.w;
        Ws[0][lk + 0][lrow] = rw.x; Ws[0][lk + 1][lrow] = rw.y;
        Ws[0][lk + 2][lrow] = rw.z; Ws[0][lk + 3][lrow] = rw.w;
    }
    __syncthreads();

    constexpr int NKT = D_ / BK;
    int buf = 0;
    for (int kt = 1; kt <= NKT; kt++) {
        float4 na, nw;
        if (kt < NKT) {
            na = *(const float4*)(Aptr + kt * BK);
            nw = *(const float4*)(Wptr + kt * BK);
        }
#pragma unroll
        for (int k = 0; k < BK; k++) {
            float4 a0 = *(const float4*)&As[buf][k][wm + trow];
            float4 a1 = *(const float4*)&As[buf][k][wm + 16 + trow];
            ulonglong2 w0 = *(const ulonglong2*)&Ws[buf][k][wn + tcol];
            ulonglong2 w1 = *(const ulonglong2*)&Ws[buf][k][wn + 32 + tcol];
            float av[8] = {a0.x, a0.y, a0.z, a0.w, a1.x, a1.y, a1.z, a1.w};
#pragma unroll
            for (int i = 0; i < 8; i++) {
                unsigned long long ad = dup2(av[i]);
                fma2(acc2[i][0], ad, w0.x);
                fma2(acc2[i][1], ad, w0.y);
                fma2(acc2[i][2], ad, w1.x);
                fma2(acc2[i][3], ad, w1.y);
            }
        }
        if (kt < NKT) {
            int nb = buf ^ 1;
            As[nb][lk + 0][lrow] = na.x; As[nb][lk + 1][lrow] = na.y;
            As[nb][lk + 2][lrow] = na.z; As[nb][lk + 3][lrow] = na.w;
            Ws[nb][lk + 0][lrow] = nw.x; Ws[nb][lk + 1][lrow] = nw.y;
            Ws[nb][lk + 2][lrow] = nw.z; Ws[nb][lk + 3][lrow] = nw.w;
        }
        __syncthreads();
        buf ^= 1;
    }

    float4 bb0 = *(const float4*)&bias[n0 + wn + tcol];
    float4 bb1 = *(const float4*)&bias[n0 + wn + 32 + tcol];
#pragma unroll
    for (int i = 0; i < 8; i++) {
        int mi = wm + ((i < 4) ? (trow + i) : (16 + trow + i - 4));
        float* cp = C + (size_t)(m0 + mi) * D_ + n0;
        float2 p0 = unpk(acc2[i][0]);
        float2 p1 = unpk(acc2[i][1]);
        float2 p2 = unpk(acc2[i][2]);
        float2 p3 = unpk(acc2[i][3]);
        float4 o0 = make_float4(p0.x + bb0.x, p0.y + bb0.y,
                                p1.x + bb0.z, p1.y + bb0.w);
        float4 o1 = make_float4(p2.x + bb1.x, p2.y + bb1.y,
                                p3.x + bb1.z, p3.y + bb1.w);
        *(float4*)(cp + wn + tcol) = o0;
        *(float4*)(cp + wn + 32 + tcol) = o1;
    }
}

// ---------------------------------------------------------------------------
// h0 -> H[0]
// ---------------------------------------------------------------------------
__global__ void copy_h0_kernel(const float* __restrict__ h0, float* __restrict__ H)
{
    int i = blockIdx.x * blockDim.x + threadIdx.x;
    if (i < B_ * D_) H[i] = h0[i];
}

// ---------------------------------------------------------------------------
// Persistent recurrent scan, round-5 structure.
// 128 CTAs x 512 threads; CTA owns 8 columns. Weights cached ONCE in SMEM,
// interleaved (R_h, R_delta) as float2 pairs -> one fma.rn.f32x2 per (k,j)
// computes both dot products. Each warp owns a 64-wide K-slice: it stages its
// own h slice (coalesced LDG -> STS), then computes all 8 columns with
// broadcast (uniform-address) weight LDS -> crossbar traffic /10 vs round 4.
// Split-K partials reduced via padded SMEM; 256 epilogue threads apply gates.
// ---------------------------------------------------------------------------
constexpr int NCTA = 128;
constexpr int JC = 8;                        // columns per CTA
constexpr int SB_ = 512;                     // threads per CTA
constexpr int H4S = 257;                     // float4 stride per batch row
constexpr int WVD_F = JC * D_ * 2;           // 16384 floats (interleaved pairs)
constexpr int HS_F = B_ * H4S * 4;           // 32896 floats
constexpr int RED_ROW = 33;                  // u64 per row (padded)
constexpr int RED_F = 16 * JC * RED_ROW * 2; // 8448 floats
constexpr int SMEM_FLOATS = WVD_F + HS_F + RED_F;
constexpr int SMEM_BYTES = SMEM_FLOATS * 4;  // 230912 B

__device__ volatile unsigned g_arrive[NCTA * 32];  // one flag per CTA, 128B apart
__device__ volatile unsigned g_release;

__global__ void __launch_bounds__(SB_, 1) scan_kernel(
    const float* __restrict__ x,
    const float* __restrict__ Rh,
    const float* __restrict__ Rd,
    const float* __restrict__ bgate,
    float* __restrict__ out,
    float* __restrict__ H)
{
    extern __shared__ float sm[];
    float2* wvd2 = (float2*)sm;                       // [JC][D_] (Rh,Rd) pairs
    const ulonglong2* wvd_u2 = (const ulonglong2*)sm; // same, 2 k's per load
    float*  hsf = sm + WVD_F;                         // h as [B][H4S*4] floats
    float4* hs4 = (float4*)hsf;
    unsigned long long* red2 = (unsigned long long*)(sm + WVD_F + HS_F);

    const float* __restrict__ xr = g_scratch[0];
    const float* __restrict__ xw = g_scratch[1];

    const int cta = blockIdx.x;
    const int tid = threadIdx.x;
    const int j0 = cta * JC;

    // Cache this CTA's weights once, interleaved (Rh, Rd).
    for (int i = tid; i < JC * D_; i += SB_) {
        int j = i >> 10, k = i & 1023;
        wvd2[i] = make_float2(Rh[(size_t)(j0 + j) * D_ + k],
                              Rd[(size_t)(j0 + j) * D_ + k]);
    }
    __syncthreads();

    const int warp  = tid >> 5;      // 0..15, owns K-slice [warp*64, warp*64+64)
    const int b     = tid & 31;      // lane -> batch
    const int qbase = warp * 16;     // float4 index base of this warp's K-slice

    // epilogue mapping (tid < 256): column ej, batch eb
    const int ej = tid & 7;
    const int eb = tid >> 3;
    const int jg = j0 + ej;
    float bg = 0.f;
    if (tid < 256) bg = bgate[jg];

    for (int t = 0; t < T_; t++) {
        const size_t tb = (size_t)t * B_ * D_;

        // ---- prefetch epilogue inputs early (latency hidden by compute) ----
        float pre_xr = 0.f, pre_xw = 0.f, pre_x = 0.f;
        const size_t eidx = tb + (size_t)eb * D_ + jg;
        if (tid < 256) {
            pre_xr = __ldg(xr + eidx);
            pre_xw = __ldg(xw + eidx);
            pre_x  = __ldg(x + eidx);
        }

        // ---- per-warp h staging: this warp's K-slice, all batches ----
        const float4* hp = (const float4*)(H + tb);
#pragma unroll
        for (int it = 0; it < 16; it++) {
            int idx = it * 32 + b;          // coalesced
            int b2  = idx >> 4;
            int qq  = idx & 15;
            float4 v = __ldcg(hp + b2 * 256 + qbase + qq);
            hs4[b2 * H4S + qbase + qq] = v;
        }
        __syncwarp();

        // ---- compute: 8 columns x 2 matrices, this warp's 64 k's ----
        unsigned long long acc2[JC];
#pragma unroll
        for (int j = 0; j < JC; j++) acc2[j] = 0ull;

#pragma unroll 4
        for (int qq = 0; qq < 16; qq++) {
            int q = qbase + qq;
            float4 h4 = hs4[b * H4S + q];
            unsigned long long hx = dup2(h4.x);
            unsigned long long hy = dup2(h4.y);
            unsigned long long hz = dup2(h4.z);
            unsigned long long hw = dup2(h4.w);
#pragma unroll
            for (int j = 0; j < JC; j++) {
                ulonglong2 wA = wvd_u2[j * 512 + 2 * q];      // k=4q,4q+1
                ulonglong2 wB = wvd_u2[j * 512 + 2 * q + 1];  // k=4q+2,4q+3
                fma2(acc2[j], hx, wA.x);
                fma2(acc2[j], hy, wA.y);
                fma2(acc2[j], hz, wB.x);
                fma2(acc2[j], hw, wB.y);
            }
        }

        // ---- store split-K partials ----
#pragma unroll
        for (int j = 0; j < JC; j++)
            red2[(warp * JC + j) * RED_ROW + b] = acc2[j];
        __syncthreads();

        // ---- epilogue: reduce 16 partials, gates, write out & H[t+1] ----
        if (tid < 256) {
            float sv = pre_xr, sd = pre_xw;
#pragma unroll
            for (int w = 0; w < 16; w++) {
                float2 p = unpk(red2[(w * JC + ej) * RED_ROW + eb]);
                sv += p.x;
                sd += p.y;
            }
            float hprev = hsf[eb * (H4S * 4) + jg];
            float delta = 1.f / (1.f + __expf(-sd));
            float hv    = tanhf(sv);
            float hn    = hprev + delta * (hv - hprev);  // (1-d)*hp + d*tanh(v)
            float g     = hn + pre_x + bg;
            float sil   = g / (1.f + __expf(-g));        // silu(g)
            out[eidx] = hn * sil;
            H[eidx + (size_t)B_ * D_] = hn;              // H[t+1]
        }

        if (t == T_ - 1) break;

        // ---- grid-wide barrier: flag array + master warp + release word ----
        __threadfence();
        __syncthreads();
        const unsigned want = (unsigned)(t + 1);
        if (tid == 0) g_arrive[cta << 5] = want;
        if (cta == 0 && tid >= 32 && tid < 64) {
            int l = tid - 32;                 // each lane watches 4 CTA flags
            bool ok;
            do {
                ok = (g_arrive[(l * 4 + 0) << 5] == want)
                  && (g_arrive[(l * 4 + 1) << 5] == want)
                  && (g_arrive[(l * 4 + 2) << 5] == want)
                  && (g_arrive[(l * 4 + 3) << 5] == want);
            } while (!__all_sync(0xffffffffu, ok));
            if (l == 0) { __threadfence(); g_release = want; }
        }
        if (tid == 0) {
            while (g_release != want) { __nanosleep(32); }
        }
        __syncthreads();
    }
}

// ---------------------------------------------------------------------------
// Launch
// Inputs (metadata order): x, h0, R_h, R_x, R_delta, W_delta, b, b_delta, b_gate
// Output: outputs [T,B,D] followed by h [T+1,B,D], fp32.
// ---------------------------------------------------------------------------
extern "C" void kernel_launch(void* const* d_in, const int* in_sizes, int n_in,
                              void* d_out, int out_size)
{
    const float* x       = (const float*)d_in[0];
    const float* h0      = (const float*)d_in[1];
    const float* R_h     = (const float*)d_in[2];
    const float* R_x     = (const float*)d_in[3];
    const float* R_delta = (const float*)d_in[4];
    const float* W_delta = (const float*)d_in[5];
    const float* b       = (const float*)d_in[6];
    const float* b_delta = (const float*)d_in[7];
    const float* b_gate  = (const float*)d_in[8];

    float* out = (float*)d_out;
    float* H   = out + (size_t)T_ * B_ * D_;   // h region: [T+1, B, D]

    cudaFuncSetAttribute(scan_kernel,
                         cudaFuncAttributeMaxDynamicSharedMemorySize, SMEM_BYTES);

    dim3 ggrid(D_ / BN, M_ / BM, 2);
    gemm_bias_kernel<<<ggrid, 256>>>(x, R_x, W_delta, b, b_delta);
    copy_h0_kernel<<<(B_ * D_ + 255) / 256, 256>>>(h0, H);
    scan_kernel<<<NCTA, SB_, SMEM_BYTES>>>(x, R_h, R_delta, b_gate, out, H);
}